// round 1
// baseline (speedup 1.0000x reference)
#include <cuda_runtime.h>
#include <math.h>
#include <stdint.h>

#define D_MODEL 1024
#define NHEADS  16
#define DK      64
#define BB      2
#define TT      2048
#define MTOT    (BB*TT)   // 4096 rows

// ---------------- scratch (static device arrays; no allocation allowed) ----
__device__ float g_Qr[MTOT*D_MODEL];    // RoPE'd Q
__device__ float g_Kr[MTOT*D_MODEL];    // RoPE'd K
__device__ float g_V [MTOT*D_MODEL];    // pre-RoPE Q == V (reference uses Wq/bq for V!)
__device__ float g_Attn[MTOT*D_MODEL];  // attention output (heads merged)
__device__ float g_cos[TT*32];
__device__ float g_sin[TT*32];

// ---------------- RoPE table ----------------------------------------------
__global__ void rope_table_kernel(const int* __restrict__ pos)
{
    int t = blockIdx.x;
    int i = threadIdx.x;          // 0..31
    double inv = pow(10000.0, -((double)(2*i) / 64.0));
    float ang = (float)pos[t] * (float)inv;
    g_cos[t*32 + i] = cosf(ang);
    g_sin[t*32 + i] = sinf(ang);
}

// ---------------- Q/K projection GEMM + RoPE epilogue ----------------------
// Y[m,n] = sum_k X[m,k] * W[n,k] + b[n]; z=0 -> (Wq,bq): writes g_V (raw) and
// g_Qr (roped); z=1 -> (Wk,bk): writes g_Kr (roped).
__global__ __launch_bounds__(256) void qk_gemm_kernel(
    const float* __restrict__ X,
    const float* __restrict__ Wq, const float* __restrict__ bq,
    const float* __restrict__ Wk, const float* __restrict__ bk)
{
    __shared__ float As[8][128];
    __shared__ float Bs[8][128];

    const float* W    = (blockIdx.z == 0) ? Wq : Wk;
    const float* bias = (blockIdx.z == 0) ? bq : bk;

    const int tid = threadIdx.x;
    const int tx = tid & 15, ty = tid >> 4;
    const int m0 = blockIdx.y * 128, n0 = blockIdx.x * 128;
    const int li = tid >> 1;
    const int lk = (tid & 1) * 4;

    float acc[8][8];
    #pragma unroll
    for (int u = 0; u < 8; u++)
        #pragma unroll
        for (int v = 0; v < 8; v++) acc[u][v] = 0.f;

    const float* Xp = X + (size_t)(m0 + li) * D_MODEL + lk;
    const float* Wp = W + (size_t)(n0 + li) * D_MODEL + lk;

    for (int k0 = 0; k0 < D_MODEL; k0 += 8) {
        float4 xa = *(const float4*)(Xp + k0);
        float4 wa = *(const float4*)(Wp + k0);
        __syncthreads();
        As[lk+0][li] = xa.x; As[lk+1][li] = xa.y; As[lk+2][li] = xa.z; As[lk+3][li] = xa.w;
        Bs[lk+0][li] = wa.x; Bs[lk+1][li] = wa.y; Bs[lk+2][li] = wa.z; Bs[lk+3][li] = wa.w;
        __syncthreads();
        #pragma unroll
        for (int k = 0; k < 8; k++) {
            float a[8], bv[8];
            #pragma unroll
            for (int u = 0; u < 8; u++) a[u] = As[k][ty*8 + u];
            #pragma unroll
            for (int v = 0; v < 8; v++) bv[v] = Bs[k][tx*8 + v];
            #pragma unroll
            for (int u = 0; u < 8; u++)
                #pragma unroll
                for (int v = 0; v < 8; v++)
                    acc[u][v] += a[u] * bv[v];
        }
    }

    float* outR = (blockIdx.z == 0) ? g_Qr : g_Kr;
    const bool writeV = (blockIdx.z == 0);

    #pragma unroll
    for (int u = 0; u < 8; u++) {
        int m = m0 + ty*8 + u;
        int t = m & (TT - 1);
        const float* cr = &g_cos[t*32];
        const float* sr = &g_sin[t*32];
        float* orow = outR + (size_t)m * D_MODEL;
        float* vrow = g_V  + (size_t)m * D_MODEL;
        #pragma unroll
        for (int w = 0; w < 4; w++) {
            int n = n0 + tx*8 + 2*w;
            float y1 = acc[u][2*w]   + bias[n];
            float y2 = acc[u][2*w+1] + bias[n+1];
            if (writeV) { vrow[n] = y1; vrow[n+1] = y2; }
            int fi = (n & 63) >> 1;
            float c = cr[fi], s = sr[fi];
            orow[n]   = y1*c - y2*s;
            orow[n+1] = y1*s + y2*c;
        }
    }
}

// ---------------- flash attention (fp32 SIMT, register-tiled) --------------
#define ATT_BM 128
#define ATT_BN 64
// smem floats: Qs 64*129 + Ks 64*68 + Vs 64*68 + Ss 128*65 + 3*128
#define ATT_SMEM_FLOATS (64*129 + 64*68 + 64*68 + 128*65 + 3*128)
#define ATT_SMEM_BYTES  (ATT_SMEM_FLOATS * 4)

__global__ __launch_bounds__(256) void attn_kernel(float* __restrict__ O)
{
    extern __shared__ float sm[];
    float* Qs   = sm;                 // [d=64][i=128] pad 129
    float* Ks   = Qs + 64*129;        // [d=64][j=64]  pad 68
    float* Vs   = Ks + 64*68;         // [j=64][c=64]  pad 68
    float* Ss   = Vs + 64*68;         // [r=128][c=64] pad 65
    float* sm_m = Ss + 128*65;
    float* sm_l = sm_m + 128;
    float* sm_s = sm_l + 128;

    const int tid = threadIdx.x;
    const int tx = tid & 15, ty = tid >> 4;
    const int row0 = ty * 8;          // 8 q-rows per thread
    const int col0 = tx * 4;          // 4 cols per thread
    const int h = blockIdx.y, b = blockIdx.z;
    const int qbase = blockIdx.x * ATT_BM;
    const size_t base = (size_t)b * TT * D_MODEL + h * DK;
    const float* Qb = g_Qr + base;
    const float* Kb = g_Kr + base;
    const float* Vb = g_V  + base;

    // load Q tile (transposed to [d][i])
    for (int idx = tid; idx < ATT_BM*16; idx += 256) {
        int i = idx >> 4, d4 = (idx & 15) << 2;
        float4 q4 = *(const float4*)&Qb[(size_t)(qbase + i) * D_MODEL + d4];
        Qs[(d4+0)*129 + i] = q4.x; Qs[(d4+1)*129 + i] = q4.y;
        Qs[(d4+2)*129 + i] = q4.z; Qs[(d4+3)*129 + i] = q4.w;
    }
    if (tid < ATT_BM) { sm_m[tid] = -1e30f; sm_l[tid] = 0.f; }

    float acc[8][4];
    #pragma unroll
    for (int u = 0; u < 8; u++)
        #pragma unroll
        for (int v = 0; v < 4; v++) acc[u][v] = 0.f;

    for (int j0 = 0; j0 < qbase + ATT_BM; j0 += ATT_BN) {
        __syncthreads();   // prior PV reads of Ks/Vs/Ss done
        for (int idx = tid; idx < ATT_BN*16; idx += 256) {
            int j = idx >> 4, d4 = (idx & 15) << 2;
            float4 k4 = *(const float4*)&Kb[(size_t)(j0 + j) * D_MODEL + d4];
            Ks[(d4+0)*68 + j] = k4.x; Ks[(d4+1)*68 + j] = k4.y;
            Ks[(d4+2)*68 + j] = k4.z; Ks[(d4+3)*68 + j] = k4.w;
            float4 v4 = *(const float4*)&Vb[(size_t)(j0 + j) * D_MODEL + d4];
            *(float4*)&Vs[j*68 + d4] = v4;
        }
        __syncthreads();

        // S = Q @ K^T  (microtile 8x4 per thread)
        float s[8][4];
        #pragma unroll
        for (int u = 0; u < 8; u++)
            #pragma unroll
            for (int v = 0; v < 4; v++) s[u][v] = 0.f;
        #pragma unroll
        for (int d = 0; d < 64; d++) {
            float a[8];
            #pragma unroll
            for (int u = 0; u < 8; u++) a[u] = Qs[d*129 + row0 + u];
            float4 bv = *(const float4*)&Ks[d*68 + col0];
            #pragma unroll
            for (int u = 0; u < 8; u++) {
                s[u][0] += a[u]*bv.x; s[u][1] += a[u]*bv.y;
                s[u][2] += a[u]*bv.z; s[u][3] += a[u]*bv.w;
            }
        }
        // causal mask + scale, stage to shared
        #pragma unroll
        for (int u = 0; u < 8; u++) {
            int qi = qbase + row0 + u;
            #pragma unroll
            for (int v = 0; v < 4; v++) {
                int kj = j0 + col0 + v;
                Ss[(row0+u)*65 + col0 + v] = (kj <= qi) ? s[u][v]*0.125f : -1e30f;
            }
        }
        __syncthreads();

        // online softmax: one thread per row
        if (tid < ATT_BM) {
            float* rp = &Ss[tid*65];
            float mt = rp[0];
            #pragma unroll
            for (int c = 1; c < ATT_BN; c++) mt = fmaxf(mt, rp[c]);
            float mo = sm_m[tid];
            float mn = fmaxf(mo, mt);
            float scl = __expf(mo - mn);     // 0 when mo==-1e30, mn finite
            float ls = 0.f;
            #pragma unroll
            for (int c = 0; c < ATT_BN; c++) {
                float p = __expf(rp[c] - mn);
                rp[c] = p;
                ls += p;
            }
            sm_m[tid] = mn;
            sm_l[tid] = sm_l[tid]*scl + ls;
            sm_s[tid] = scl;
        }
        __syncthreads();

        // rescale acc, then O += P @ V
        float rs[8];
        #pragma unroll
        for (int u = 0; u < 8; u++) rs[u] = sm_s[row0 + u];
        #pragma unroll
        for (int u = 0; u < 8; u++)
            #pragma unroll
            for (int v = 0; v < 4; v++) acc[u][v] *= rs[u];
        #pragma unroll
        for (int j = 0; j < ATT_BN; j++) {
            float a[8];
            #pragma unroll
            for (int u = 0; u < 8; u++) a[u] = Ss[(row0+u)*65 + j];
            float4 bv = *(const float4*)&Vs[j*68 + col0];
            #pragma unroll
            for (int u = 0; u < 8; u++) {
                acc[u][0] += a[u]*bv.x; acc[u][1] += a[u]*bv.y;
                acc[u][2] += a[u]*bv.z; acc[u][3] += a[u]*bv.w;
            }
        }
    }

    // finalize: divide by l, write out (sm_l final; last sync was pre-PV)
    #pragma unroll
    for (int u = 0; u < 8; u++) {
        int r = row0 + u;
        float il = 1.f / sm_l[r];
        float4 o4;
        o4.x = acc[u][0]*il; o4.y = acc[u][1]*il;
        o4.z = acc[u][2]*il; o4.w = acc[u][3]*il;
        *(float4*)&O[base + (size_t)(qbase + r) * D_MODEL + col0] = o4;
    }
}

// ---------------- output projection ----------------------------------------
__global__ __launch_bounds__(256) void o_gemm_kernel(
    const float* __restrict__ W, const float* __restrict__ bias,
    float* __restrict__ Y)
{
    __shared__ float As[8][128];
    __shared__ float Bs[8][128];

    const int tid = threadIdx.x;
    const int tx = tid & 15, ty = tid >> 4;
    const int m0 = blockIdx.y * 128, n0 = blockIdx.x * 128;
    const int li = tid >> 1;
    const int lk = (tid & 1) * 4;

    float acc[8][8];
    #pragma unroll
    for (int u = 0; u < 8; u++)
        #pragma unroll
        for (int v = 0; v < 8; v++) acc[u][v] = 0.f;

    const float* Xp = g_Attn + (size_t)(m0 + li) * D_MODEL + lk;
    const float* Wp = W      + (size_t)(n0 + li) * D_MODEL + lk;

    for (int k0 = 0; k0 < D_MODEL; k0 += 8) {
        float4 xa = *(const float4*)(Xp + k0);
        float4 wa = *(const float4*)(Wp + k0);
        __syncthreads();
        As[lk+0][li] = xa.x; As[lk+1][li] = xa.y; As[lk+2][li] = xa.z; As[lk+3][li] = xa.w;
        Bs[lk+0][li] = wa.x; Bs[lk+1][li] = wa.y; Bs[lk+2][li] = wa.z; Bs[lk+3][li] = wa.w;
        __syncthreads();
        #pragma unroll
        for (int k = 0; k < 8; k++) {
            float a[8], bv[8];
            #pragma unroll
            for (int u = 0; u < 8; u++) a[u] = As[k][ty*8 + u];
            #pragma unroll
            for (int v = 0; v < 8; v++) bv[v] = Bs[k][tx*8 + v];
            #pragma unroll
            for (int u = 0; u < 8; u++)
                #pragma unroll
                for (int v = 0; v < 8; v++)
                    acc[u][v] += a[u] * bv[v];
        }
    }

    #pragma unroll
    for (int u = 0; u < 8; u++) {
        int m = m0 + ty*8 + u;
        float* yrow = Y + (size_t)m * D_MODEL;
        #pragma unroll
        for (int v = 0; v < 8; v++) {
            int n = n0 + tx*8 + v;
            yrow[n] = acc[u][v] + bias[n];
        }
    }
}

// ---------------- launch ----------------------------------------------------
extern "C" void kernel_launch(void* const* d_in, const int* in_sizes, int n_in,
                              void* d_out, int out_size)
{
    (void)in_sizes; (void)n_in; (void)out_size;
    const float* x   = (const float*)d_in[0];
    const int*   pos = (const int*)  d_in[1];
    const float* Wq  = (const float*)d_in[2];
    const float* bq  = (const float*)d_in[3];
    const float* Wk  = (const float*)d_in[4];
    const float* bk  = (const float*)d_in[5];
    // d_in[6], d_in[7] (Wv, bv) are unused by the reference (V uses Wq/bq)
    const float* Wo  = (const float*)d_in[8];
    const float* bo  = (const float*)d_in[9];
    float* out = (float*)d_out;

    cudaFuncSetAttribute(attn_kernel,
                         cudaFuncAttributeMaxDynamicSharedMemorySize,
                         ATT_SMEM_BYTES);

    rope_table_kernel<<<TT, 32>>>(pos);

    dim3 gq(D_MODEL/128, MTOT/128, 2);
    qk_gemm_kernel<<<gq, 256>>>(x, Wq, bq, Wk, bk);

    float* attn_out_sym;
    cudaGetSymbolAddress((void**)&attn_out_sym, g_Attn);
    dim3 ga(TT/ATT_BM, NHEADS, BB);
    attn_kernel<<<ga, 256, ATT_SMEM_BYTES>>>(attn_out_sym);

    dim3 go(D_MODEL/128, MTOT/128, 1);
    o_gemm_kernel<<<go, 256>>>(Wo, bo, out);
}

// round 2
// speedup vs baseline: 3.0914x; 3.0914x over previous
#include <cuda_runtime.h>
#include <math.h>
#include <stdint.h>

#define D_MODEL 1024
#define NHEADS  16
#define DK      64
#define BB      2
#define TT      2048
#define MTOT    (BB*TT)   // 4096 rows

// ---------------- scratch (static device arrays; no allocation allowed) ----
__device__ float g_Qr[MTOT*D_MODEL];    // RoPE'd Q
__device__ float g_Kr[MTOT*D_MODEL];    // RoPE'd K
__device__ float g_V [MTOT*D_MODEL];    // pre-RoPE Q == V (reference uses Wq/bq for V!)
__device__ float g_Attn[MTOT*D_MODEL];  // attention output (heads merged)
__device__ float g_cos[TT*32];
__device__ float g_sin[TT*32];

// ---------------- helpers ---------------------------------------------------
__device__ __forceinline__ uint32_t f2tf(float x)
{
    uint32_t u;
    asm("cvt.rna.tf32.f32 %0, %1;" : "=r"(u) : "f"(x));
    return u;
}

__device__ __forceinline__ void mma8(float4& c,
    uint32_t a0, uint32_t a1, uint32_t a2, uint32_t a3,
    uint32_t b0, uint32_t b1)
{
    asm volatile(
        "mma.sync.aligned.m16n8k8.row.col.f32.tf32.tf32.f32 "
        "{%0,%1,%2,%3}, {%4,%5,%6,%7}, {%8,%9}, {%0,%1,%2,%3};\n"
        : "+f"(c.x), "+f"(c.y), "+f"(c.z), "+f"(c.w)
        : "r"(a0), "r"(a1), "r"(a2), "r"(a3), "r"(b0), "r"(b1));
}

// ---------------- RoPE table ----------------------------------------------
__global__ void rope_table_kernel(const int* __restrict__ pos)
{
    int t = blockIdx.x;
    int i = threadIdx.x;          // 0..31
    double inv = pow(10000.0, -((double)(2*i) / 64.0));
    float ang = (float)pos[t] * (float)inv;
    g_cos[t*32 + i] = cosf(ang);
    g_sin[t*32 + i] = sinf(ang);
}

// ---------------- TF32 mma GEMM: Q/K projection + RoPE epilogue -------------
// Y[m,n] = sum_k X[m,k] * W[n,k] + b[n]
// z=0 -> (Wq,bq): writes g_V (raw) and g_Qr (roped); z=1 -> (Wk,bk): g_Kr.
#define GLD 36   // smem leading dim (floats): conflict-free frags + 16B aligned

__global__ __launch_bounds__(256) void qk_gemm_kernel(
    const float* __restrict__ X,
    const float* __restrict__ Wq, const float* __restrict__ bq,
    const float* __restrict__ Wk, const float* __restrict__ bk)
{
    __shared__ uint32_t As[128*GLD];
    __shared__ uint32_t Bs[128*GLD];

    const float* W    = blockIdx.z ? Wk : Wq;
    const float* bias = blockIdx.z ? bk : bq;

    const int tid = threadIdx.x, lane = tid & 31, warp = tid >> 5;
    const int wm = warp >> 2, wn = warp & 3;     // 2 x 4 warp grid
    const int g = lane >> 2, t = lane & 3;
    const int m0 = blockIdx.y * 128, n0 = blockIdx.x * 128;

    float4 acc[4][4];
    #pragma unroll
    for (int i = 0; i < 4; i++)
        #pragma unroll
        for (int j = 0; j < 4; j++) acc[i][j] = make_float4(0.f,0.f,0.f,0.f);

    const int srow = tid >> 3;          // 0..31, + i*32
    const int sc4  = (tid & 7) * 4;     // 0..28
    const float* Xp = X + (size_t)(m0 + srow) * D_MODEL + sc4;
    const float* Wp = W + (size_t)(n0 + srow) * D_MODEL + sc4;

    float4 ra[4], rb[4];
    #pragma unroll
    for (int i = 0; i < 4; i++) {
        ra[i] = *(const float4*)(Xp + (size_t)(i*32) * D_MODEL);
        rb[i] = *(const float4*)(Wp + (size_t)(i*32) * D_MODEL);
    }

    for (int k0 = 0; k0 < D_MODEL; k0 += 32) {
        __syncthreads();   // prior compute done reading smem
        #pragma unroll
        for (int i = 0; i < 4; i++) {
            uint32_t* pa = &As[(srow + i*32)*GLD + sc4];
            pa[0]=f2tf(ra[i].x); pa[1]=f2tf(ra[i].y); pa[2]=f2tf(ra[i].z); pa[3]=f2tf(ra[i].w);
            uint32_t* pb = &Bs[(srow + i*32)*GLD + sc4];
            pb[0]=f2tf(rb[i].x); pb[1]=f2tf(rb[i].y); pb[2]=f2tf(rb[i].z); pb[3]=f2tf(rb[i].w);
        }
        __syncthreads();
        if (k0 + 32 < D_MODEL) {
            #pragma unroll
            for (int i = 0; i < 4; i++) {
                ra[i] = *(const float4*)(Xp + k0 + 32 + (size_t)(i*32) * D_MODEL);
                rb[i] = *(const float4*)(Wp + k0 + 32 + (size_t)(i*32) * D_MODEL);
            }
        }
        #pragma unroll
        for (int ks = 0; ks < 4; ks++) {
            const int kk = ks * 8;
            uint32_t af[4][4];
            #pragma unroll
            for (int mt = 0; mt < 4; mt++) {
                int rm = wm*64 + mt*16;
                af[mt][0] = As[(rm+g  )*GLD + kk + t];
                af[mt][1] = As[(rm+g+8)*GLD + kk + t];
                af[mt][2] = As[(rm+g  )*GLD + kk + t + 4];
                af[mt][3] = As[(rm+g+8)*GLD + kk + t + 4];
            }
            #pragma unroll
            for (int nt = 0; nt < 4; nt++) {
                int cn = wn*32 + nt*8;
                uint32_t b0 = Bs[(cn+g)*GLD + kk + t];
                uint32_t b1 = Bs[(cn+g)*GLD + kk + t + 4];
                #pragma unroll
                for (int mt = 0; mt < 4; mt++)
                    mma8(acc[mt][nt], af[mt][0],af[mt][1],af[mt][2],af[mt][3], b0, b1);
            }
        }
    }

    float* outR = blockIdx.z ? g_Kr : g_Qr;
    const bool writeV = (blockIdx.z == 0);

    #pragma unroll
    for (int mt = 0; mt < 4; mt++) {
        int r1 = m0 + wm*64 + mt*16 + g;
        int r2 = r1 + 8;
        int t1 = r1 & (TT-1), t2 = r2 & (TT-1);
        #pragma unroll
        for (int nt = 0; nt < 4; nt++) {
            int n = n0 + wn*32 + nt*8 + 2*t;
            float b0v = bias[n], b1v = bias[n+1];
            int fi = (n & 63) >> 1;
            float4 c = acc[mt][nt];
            float y1 = c.x + b0v, y2 = c.y + b1v;
            float z1 = c.z + b0v, z2 = c.w + b1v;
            if (writeV) {
                *(float2*)&g_V[(size_t)r1*D_MODEL + n] = make_float2(y1, y2);
                *(float2*)&g_V[(size_t)r2*D_MODEL + n] = make_float2(z1, z2);
            }
            float c1 = g_cos[t1*32+fi], s1 = g_sin[t1*32+fi];
            float c2 = g_cos[t2*32+fi], s2 = g_sin[t2*32+fi];
            *(float2*)&outR[(size_t)r1*D_MODEL + n] =
                make_float2(y1*c1 - y2*s1, y1*s1 + y2*c1);
            *(float2*)&outR[(size_t)r2*D_MODEL + n] =
                make_float2(z1*c2 - z2*s2, z1*s2 + z2*c2);
        }
    }
}

// ---------------- flash attention (TF32 mma) --------------------------------
#define ALD 68   // smem ld: conflict-free frag reads, 16B-aligned staging
#define ATT_SMEM_BYTES ((64*ALD + 64*ALD + 128*ALD) * 4)   // Ks + Vs + Ss

__global__ __launch_bounds__(256) void attn_kernel(float* __restrict__ O)
{
    extern __shared__ uint32_t sm[];
    uint32_t* Ks = sm;              // [j=64][d..ALD]  (B col-major for S)
    uint32_t* Vs = Ks + 64*ALD;     // [c=64][j..ALD]  (V transposed)
    uint32_t* Ss = Vs + 64*ALD;     // [r=128][c..ALD] (P staged for PV)

    const int tid = threadIdx.x, lane = tid & 31, warp = tid >> 5;
    const int g = lane >> 2, t = lane & 3;
    const int h = blockIdx.y, b = blockIdx.z;
    const int qbase = (gridDim.x - 1 - blockIdx.x) * 128;  // big tiles first
    const size_t base = (size_t)b * TT * D_MODEL + h * DK;
    const float* Qb = g_Qr + base;
    const float* Kb = g_Kr + base;
    const float* Vb = g_V  + base;

    // Q fragments in registers: warp handles rows [warp*16, warp*16+16)
    uint32_t qa[8][4];
    {
        const float* q1 = Qb + (size_t)(qbase + warp*16 + g) * D_MODEL;
        const float* q2 = q1 + (size_t)8 * D_MODEL;
        #pragma unroll
        for (int ks = 0; ks < 8; ks++) {
            qa[ks][0] = f2tf(__ldg(q1 + ks*8 + t));
            qa[ks][1] = f2tf(__ldg(q2 + ks*8 + t));
            qa[ks][2] = f2tf(__ldg(q1 + ks*8 + t + 4));
            qa[ks][3] = f2tf(__ldg(q2 + ks*8 + t + 4));
        }
    }

    float4 oacc[8];
    #pragma unroll
    for (int nt = 0; nt < 8; nt++) oacc[nt] = make_float4(0.f,0.f,0.f,0.f);
    float m0p = -1e30f, m1p = -1e30f, l0 = 0.f, l1 = 0.f;

    const int qi1 = qbase + warp*16 + g;
    const int qi2 = qi1 + 8;
    const int nkv = (qbase + 128) / 64;

    for (int jt = 0; jt < nkv; jt++) {
        const int j0 = jt * 64;
        __syncthreads();   // prior tile's smem reads done
        // stage K (as-is) and V (transposed), tf32
        #pragma unroll
        for (int i = 0; i < 4; i++) {
            int id = tid + i*256;
            int j = id >> 4, d4 = (id & 15) * 4;
            float4 k4 = *(const float4*)&Kb[(size_t)(j0+j)*D_MODEL + d4];
            uint32_t* pk = &Ks[j*ALD + d4];
            pk[0]=f2tf(k4.x); pk[1]=f2tf(k4.y); pk[2]=f2tf(k4.z); pk[3]=f2tf(k4.w);
            float4 v4 = *(const float4*)&Vb[(size_t)(j0+j)*D_MODEL + d4];
            Vs[(d4+0)*ALD + j] = f2tf(v4.x);
            Vs[(d4+1)*ALD + j] = f2tf(v4.y);
            Vs[(d4+2)*ALD + j] = f2tf(v4.z);
            Vs[(d4+3)*ALD + j] = f2tf(v4.w);
        }
        __syncthreads();

        // S = Q @ K^T (warp rows x 64 cols)
        float4 sacc[8];
        #pragma unroll
        for (int nt = 0; nt < 8; nt++) sacc[nt] = make_float4(0.f,0.f,0.f,0.f);
        #pragma unroll
        for (int ks = 0; ks < 8; ks++) {
            #pragma unroll
            for (int nt = 0; nt < 8; nt++) {
                uint32_t b0 = Ks[(nt*8+g)*ALD + ks*8 + t];
                uint32_t b1 = Ks[(nt*8+g)*ALD + ks*8 + t + 4];
                mma8(sacc[nt], qa[ks][0], qa[ks][1], qa[ks][2], qa[ks][3], b0, b1);
            }
        }

        // mask + scale + online softmax (all in registers)
        float mx0 = -1e30f, mx1 = -1e30f;
        #pragma unroll
        for (int nt = 0; nt < 8; nt++) {
            int cj = j0 + nt*8 + 2*t;
            float4& c = sacc[nt];
            c.x = (cj     <= qi1) ? c.x * 0.125f : -1e30f;
            c.y = (cj + 1 <= qi1) ? c.y * 0.125f : -1e30f;
            c.z = (cj     <= qi2) ? c.z * 0.125f : -1e30f;
            c.w = (cj + 1 <= qi2) ? c.w * 0.125f : -1e30f;
            mx0 = fmaxf(mx0, fmaxf(c.x, c.y));
            mx1 = fmaxf(mx1, fmaxf(c.z, c.w));
        }
        mx0 = fmaxf(mx0, __shfl_xor_sync(0xffffffffu, mx0, 1));
        mx0 = fmaxf(mx0, __shfl_xor_sync(0xffffffffu, mx0, 2));
        mx1 = fmaxf(mx1, __shfl_xor_sync(0xffffffffu, mx1, 1));
        mx1 = fmaxf(mx1, __shfl_xor_sync(0xffffffffu, mx1, 2));

        float mn0 = fmaxf(m0p, mx0), mn1 = fmaxf(m1p, mx1);
        float scl0 = __expf(m0p - mn0), scl1 = __expf(m1p - mn1);
        m0p = mn0; m1p = mn1;

        float ls0 = 0.f, ls1 = 0.f;
        uint32_t* srow1 = &Ss[(warp*16 + g    )*ALD];
        uint32_t* srow2 = &Ss[(warp*16 + g + 8)*ALD];
        #pragma unroll
        for (int nt = 0; nt < 8; nt++) {
            float4 c = sacc[nt];
            float p0 = __expf(c.x - mn0), p1 = __expf(c.y - mn0);
            float p2 = __expf(c.z - mn1), p3 = __expf(c.w - mn1);
            ls0 += p0 + p1; ls1 += p2 + p3;
            int cc = nt*8 + 2*t;
            srow1[cc] = f2tf(p0); srow1[cc+1] = f2tf(p1);
            srow2[cc] = f2tf(p2); srow2[cc+1] = f2tf(p3);
        }
        ls0 += __shfl_xor_sync(0xffffffffu, ls0, 1);
        ls0 += __shfl_xor_sync(0xffffffffu, ls0, 2);
        ls1 += __shfl_xor_sync(0xffffffffu, ls1, 1);
        ls1 += __shfl_xor_sync(0xffffffffu, ls1, 2);
        l0 = l0*scl0 + ls0;
        l1 = l1*scl1 + ls1;

        #pragma unroll
        for (int nt = 0; nt < 8; nt++) {
            oacc[nt].x *= scl0; oacc[nt].y *= scl0;
            oacc[nt].z *= scl1; oacc[nt].w *= scl1;
        }
        __syncwarp();   // P rows are warp-private: STS -> cross-lane LDS fence

        // O += P @ V
        #pragma unroll
        for (int ks = 0; ks < 8; ks++) {
            uint32_t a0 = srow1[ks*8 + t];
            uint32_t a1 = srow2[ks*8 + t];
            uint32_t a2 = srow1[ks*8 + t + 4];
            uint32_t a3 = srow2[ks*8 + t + 4];
            #pragma unroll
            for (int nt = 0; nt < 8; nt++) {
                uint32_t b0 = Vs[(nt*8+g)*ALD + ks*8 + t];
                uint32_t b1 = Vs[(nt*8+g)*ALD + ks*8 + t + 4];
                mma8(oacc[nt], a0, a1, a2, a3, b0, b1);
            }
        }
    }

    // finalize
    float il0 = 1.f / l0, il1 = 1.f / l1;
    const size_t r1off = base + (size_t)qi1 * D_MODEL;
    const size_t r2off = base + (size_t)qi2 * D_MODEL;
    #pragma unroll
    for (int nt = 0; nt < 8; nt++) {
        int col = nt*8 + 2*t;
        *(float2*)&O[r1off + col] = make_float2(oacc[nt].x*il0, oacc[nt].y*il0);
        *(float2*)&O[r2off + col] = make_float2(oacc[nt].z*il1, oacc[nt].w*il1);
    }
}

// ---------------- output projection (TF32 mma) ------------------------------
__global__ __launch_bounds__(256) void o_gemm_kernel(
    const float* __restrict__ W, const float* __restrict__ bias,
    float* __restrict__ Y)
{
    __shared__ uint32_t As[128*GLD];
    __shared__ uint32_t Bs[128*GLD];

    const int tid = threadIdx.x, lane = tid & 31, warp = tid >> 5;
    const int wm = warp >> 2, wn = warp & 3;
    const int g = lane >> 2, t = lane & 3;
    const int m0 = blockIdx.y * 128, n0 = blockIdx.x * 128;

    float4 acc[4][4];
    #pragma unroll
    for (int i = 0; i < 4; i++)
        #pragma unroll
        for (int j = 0; j < 4; j++) acc[i][j] = make_float4(0.f,0.f,0.f,0.f);

    const int srow = tid >> 3;
    const int sc4  = (tid & 7) * 4;
    const float* Xp = g_Attn + (size_t)(m0 + srow) * D_MODEL + sc4;
    const float* Wp = W      + (size_t)(n0 + srow) * D_MODEL + sc4;

    float4 ra[4], rb[4];
    #pragma unroll
    for (int i = 0; i < 4; i++) {
        ra[i] = *(const float4*)(Xp + (size_t)(i*32) * D_MODEL);
        rb[i] = *(const float4*)(Wp + (size_t)(i*32) * D_MODEL);
    }

    for (int k0 = 0; k0 < D_MODEL; k0 += 32) {
        __syncthreads();
        #pragma unroll
        for (int i = 0; i < 4; i++) {
            uint32_t* pa = &As[(srow + i*32)*GLD + sc4];
            pa[0]=f2tf(ra[i].x); pa[1]=f2tf(ra[i].y); pa[2]=f2tf(ra[i].z); pa[3]=f2tf(ra[i].w);
            uint32_t* pb = &Bs[(srow + i*32)*GLD + sc4];
            pb[0]=f2tf(rb[i].x); pb[1]=f2tf(rb[i].y); pb[2]=f2tf(rb[i].z); pb[3]=f2tf(rb[i].w);
        }
        __syncthreads();
        if (k0 + 32 < D_MODEL) {
            #pragma unroll
            for (int i = 0; i < 4; i++) {
                ra[i] = *(const float4*)(Xp + k0 + 32 + (size_t)(i*32) * D_MODEL);
                rb[i] = *(const float4*)(Wp + k0 + 32 + (size_t)(i*32) * D_MODEL);
            }
        }
        #pragma unroll
        for (int ks = 0; ks < 4; ks++) {
            const int kk = ks * 8;
            uint32_t af[4][4];
            #pragma unroll
            for (int mt = 0; mt < 4; mt++) {
                int rm = wm*64 + mt*16;
                af[mt][0] = As[(rm+g  )*GLD + kk + t];
                af[mt][1] = As[(rm+g+8)*GLD + kk + t];
                af[mt][2] = As[(rm+g  )*GLD + kk + t + 4];
                af[mt][3] = As[(rm+g+8)*GLD + kk + t + 4];
            }
            #pragma unroll
            for (int nt = 0; nt < 4; nt++) {
                int cn = wn*32 + nt*8;
                uint32_t b0 = Bs[(cn+g)*GLD + kk + t];
                uint32_t b1 = Bs[(cn+g)*GLD + kk + t + 4];
                #pragma unroll
                for (int mt = 0; mt < 4; mt++)
                    mma8(acc[mt][nt], af[mt][0],af[mt][1],af[mt][2],af[mt][3], b0, b1);
            }
        }
    }

    #pragma unroll
    for (int mt = 0; mt < 4; mt++) {
        int r1 = m0 + wm*64 + mt*16 + g;
        int r2 = r1 + 8;
        #pragma unroll
        for (int nt = 0; nt < 4; nt++) {
            int n = n0 + wn*32 + nt*8 + 2*t;
            float b0v = bias[n], b1v = bias[n+1];
            float4 c = acc[mt][nt];
            *(float2*)&Y[(size_t)r1*D_MODEL + n] = make_float2(c.x + b0v, c.y + b1v);
            *(float2*)&Y[(size_t)r2*D_MODEL + n] = make_float2(c.z + b0v, c.w + b1v);
        }
    }
}

// ---------------- launch ----------------------------------------------------
extern "C" void kernel_launch(void* const* d_in, const int* in_sizes, int n_in,
                              void* d_out, int out_size)
{
    (void)in_sizes; (void)n_in; (void)out_size;
    const float* x   = (const float*)d_in[0];
    const int*   pos = (const int*)  d_in[1];
    const float* Wq  = (const float*)d_in[2];
    const float* bq  = (const float*)d_in[3];
    const float* Wk  = (const float*)d_in[4];
    const float* bk  = (const float*)d_in[5];
    // d_in[6], d_in[7] (Wv, bv) unused: reference computes V with Wq/bq
    const float* Wo  = (const float*)d_in[8];
    const float* bo  = (const float*)d_in[9];
    float* out = (float*)d_out;

    cudaFuncSetAttribute(attn_kernel,
                         cudaFuncAttributeMaxDynamicSharedMemorySize,
                         ATT_SMEM_BYTES);

    rope_table_kernel<<<TT, 32>>>(pos);

    dim3 gq(D_MODEL/128, MTOT/128, 2);
    qk_gemm_kernel<<<gq, 256>>>(x, Wq, bq, Wk, bk);

    float* attn_out_sym;
    cudaGetSymbolAddress((void**)&attn_out_sym, g_Attn);
    dim3 ga(TT/128, NHEADS, BB);
    attn_kernel<<<ga, 256, ATT_SMEM_BYTES>>>(attn_out_sym);

    dim3 go(D_MODEL/128, MTOT/128, 1);
    o_gemm_kernel<<<go, 256>>>(Wo, bo, out);
}